// round 13
// baseline (speedup 1.0000x reference)
#include <cuda_runtime.h>
#include <stdint.h>

#define REP      640
#define ROWS     16
#define NQUAD    4              // row quads per CTA
#define NSEG     8              // warp groups (4 quads x 8 segs = 32 warps)
#define NBIN     32             // 32-channel output bins (out_dim <= 1024)
#define MAXM     32768
#define MAXSTEP  1024           // M/32

// -------- device-global scratch --------
__device__ __align__(8) uint2 g_prog[MAXSTEP];   // bin-ordered {a|b<<10, cg}
__device__ int g_binptr[NBIN + 1];
__device__ int g_segbin[NSEG + 1];               // bin ranges per warp group
__device__ int g_S;
__device__ int g_nblk;
__device__ int g_irregular;
__device__ int g_is64;

__device__ __forceinline__ int geti(const void* p, int i, int is64) {
    return is64 ? (int)((const long long*)p)[i] : ((const int*)p)[i];
}

// ---- prep: heads at lane 0, continuity via shfl; bin; balanced seg split ----
__global__ void k_prep(const void* __restrict__ r1, const void* __restrict__ r2,
                       const void* __restrict__ ro, const float* __restrict__ cg,
                       int M, int out_dim) {
    __shared__ unsigned sab[MAXSTEP], scgv[MAXSTEP];
    __shared__ unsigned short sbin[MAXSTEP], spos[MAXSTEP];
    __shared__ int scnt[NBIN], sbase[NBIN + 1];
    __shared__ unsigned s_or;
    __shared__ int s_irr;
    int t = threadIdx.x;
    int lane = t & 31;
    const unsigned* cgu = (const unsigned*)cg;

    if (t < NBIN) scnt[t] = 0;
    if (t == 0) { s_or = 0u; s_irr = ((M & 31) || M > MAXM) ? 1 : 0; }
    __syncthreads();
    int Mc = (M > MAXM) ? MAXM : M;

    // int64 detect: odd 32-bit words of ro all zero -> int64
    {
        const unsigned* rr = (const unsigned*)ro;
        int lim = (Mc < 4096) ? Mc : 4096;
        unsigned v = 0;
        for (int i = 1 + 2 * t; i < lim; i += 2048) v |= rr[i];
        if (v) s_or = 1u;
    }
    __syncthreads();
    int is64 = (s_or == 0u);
    if (t == 0) g_is64 = is64;

    // verify + emit: i = base + t, so i%32 == lane; lane0 = step head
    for (int base = 0; base < Mc; base += 1024) {
        int i = base + t;
        int act = (i < Mc);
        int a = 0, b = 0, o = 0; unsigned cv = 0u;
        if (act) {
            a = geti(r1, i, is64); b = geti(r2, i, is64);
            o = geti(ro, i, is64); cv = cgu[i];
        }
        int pa = __shfl_up_sync(0xffffffffu, a, 1);
        int pb = __shfl_up_sync(0xffffffffu, b, 1);
        int po = __shfl_up_sync(0xffffffffu, o, 1);
        unsigned pc = __shfl_up_sync(0xffffffffu, cv, 1);
        if (act) {
            if (lane) {
                if (a != pa + 1 || b != pb + 1 || o != po + 1 || cv != pc)
                    s_irr = 1;
            } else {
                int s = i >> 5;
                int bin = o >> 5;
                if ((o & 31) || (unsigned)a > (unsigned)(REP - 32) ||
                    (unsigned)b > (unsigned)(REP - 32) || (unsigned)bin >= NBIN) {
                    s_irr = 1; a = 0; b = 0; bin = 0;
                }
                sab[s]  = (unsigned)a | ((unsigned)b << 10);
                scgv[s] = cv;
                sbin[s] = (unsigned short)bin;
                spos[s] = (unsigned short)atomicAdd(&scnt[bin], 1);
            }
        }
    }
    __syncthreads();

    // warp-0 shuffle scan over bins
    if (t < 32) {
        int v = scnt[t], inc = v;
        for (int off = 1; off < 32; off <<= 1) {
            int u = __shfl_up_sync(0xffffffffu, inc, off);
            if (t >= off) inc += u;
        }
        sbase[t] = inc - v;
        if (t == 31) sbase[32] = inc;
    }
    __syncthreads();

    int S = Mc >> 5;
    int nblk = (out_dim + 31) >> 5;
    if (nblk > NBIN) nblk = NBIN;
    if (t == 0) {
        g_irregular = s_irr;
        g_S = S;
        g_nblk = nblk;
        // balanced, monotone seg->bin boundaries by cumulative step count
        g_segbin[0] = 0; g_segbin[NSEG] = nblk;
        int prev = 0;
        for (int k = 1; k < NSEG; ++k) {
            int target = (S * k) / NSEG, best = prev, bd = 1 << 30;
            for (int bq = prev; bq <= nblk; ++bq) {
                int d = sbase[bq] - target; if (d < 0) d = -d;
                if (d < bd) { bd = d; best = bq; }
            }
            g_segbin[k] = best;
            prev = best;
        }
        for (int bq = 0; bq <= NBIN; ++bq) g_binptr[bq] = sbase[bq];
    }
    __syncthreads();

    // scatter steps into bin-ordered program
    for (int s = t; s < S; s += 1024)
        g_prog[sbase[sbin[s]] + spos[s]] = make_uint2(sab[s], scgv[s]);
}

// ---- main: warp = row quad, bin-outer / step-inner, program in smem ----
__global__ __launch_bounds__(1024, 2)
void k_main(const float* __restrict__ x1, const float* __restrict__ x2,
            float* __restrict__ out, int N, int out_dim,
            const void* __restrict__ r1, const void* __restrict__ r2,
            const void* __restrict__ ro, const float* __restrict__ cg, int M) {
    extern __shared__ __align__(16) char smraw[];
    int tid  = threadIdx.x;
    int lane = tid & 31;
    int w    = tid >> 5;
    int rowbase = blockIdx.x * ROWS;

    if (!g_irregular) {
        float4* xs1 = (float4*)smraw;                    // [NQUAD][REP]
        float4* xs2 = xs1 + NQUAD * REP;
        uint2*  sprog = (uint2*)(smraw + 2 * NQUAD * REP * 16);
        int*    sbptr = (int*)(sprog + MAXSTEP);         // NBIN+1
        int*    sseg  = sbptr + NBIN + 1;                // NSEG+1

        int S = g_S;
        if (rowbase + ROWS <= N) {
            for (int i = tid; i < NQUAD * REP; i += 1024) {
                int q = i / REP, c = i - q * REP;
                const float* b1 = x1 + (size_t)(rowbase + 4 * q) * REP + c;
                const float* b2 = x2 + (size_t)(rowbase + 4 * q) * REP + c;
                xs1[i] = make_float4(b1[0], b1[REP], b1[2 * REP], b1[3 * REP]);
                xs2[i] = make_float4(b2[0], b2[REP], b2[2 * REP], b2[3 * REP]);
            }
        } else {
            for (int i = tid; i < NQUAD * REP; i += 1024) {
                int q = i / REP, c = i - q * REP;
                float v1[4], v2[4];
#pragma unroll
                for (int k = 0; k < 4; ++k) {
                    int gr = rowbase + 4 * q + k;
                    v1[k] = (gr < N) ? x1[(size_t)gr * REP + c] : 0.f;
                    v2[k] = (gr < N) ? x2[(size_t)gr * REP + c] : 0.f;
                }
                xs1[i] = make_float4(v1[0], v1[1], v1[2], v1[3]);
                xs2[i] = make_float4(v2[0], v2[1], v2[2], v2[3]);
            }
        }
        for (int i = tid; i < S; i += 1024) sprog[i] = g_prog[i];
        if (tid <= NBIN) sbptr[tid] = g_binptr[tid];
        if (tid >= 32 && tid <= 32 + NSEG) sseg[tid - 32] = g_segbin[tid - 32];
        __syncthreads();

        int quad = w & (NQUAD - 1);
        int seg  = w >> 2;
        const ulonglong2* p1 = (const ulonglong2*)xs1 + quad * REP + lane;
        const ulonglong2* p2 = p1 + NQUAD * REP;
        int gr0 = rowbase + 4 * quad;
        int full = (gr0 + 3 < N);
        float* ob = out + (size_t)gr0 * out_dim + lane;
        int od = out_dim;

        int blo = sseg[seg], bhi = sseg[seg + 1];
        for (int b = blo; b < bhi; ++b) {
            int e0 = sbptr[b], e1 = sbptr[b + 1];
            unsigned long long acc0 = 0ull, acc1 = 0ull;
#pragma unroll 2
            for (int e = e0; e < e1; ++e) {
                uint2 st = sprog[e];                       // warp-uniform LDS.64
                ulonglong2 va = p1[st.x & 1023u];
                ulonglong2 vb = p2[(st.x >> 10) & 1023u];
                unsigned long long cg2 = ((unsigned long long)st.y << 32) | st.y;
                unsigned long long m0, m1;
                asm("mul.rn.f32x2 %0, %1, %2;" : "=l"(m0) : "l"(va.x), "l"(vb.x));
                asm("fma.rn.f32x2 %0, %1, %2, %3;" : "=l"(acc0) : "l"(m0), "l"(cg2), "l"(acc0));
                asm("mul.rn.f32x2 %0, %1, %2;" : "=l"(m1) : "l"(va.y), "l"(vb.y));
                asm("fma.rn.f32x2 %0, %1, %2, %3;" : "=l"(acc1) : "l"(m1), "l"(cg2), "l"(acc1));
            }
            int o = (b << 5) + lane;
            if (o < od) {
                float* op = ob + (b << 5);
                if (full) {
                    op[0]                = __uint_as_float((unsigned)acc0);
                    op[(size_t)od]       = __uint_as_float((unsigned)(acc0 >> 32));
                    op[2 * (size_t)od]   = __uint_as_float((unsigned)acc1);
                    op[3 * (size_t)od]   = __uint_as_float((unsigned)(acc1 >> 32));
                } else {
                    if (gr0 + 0 < N) op[0]              = __uint_as_float((unsigned)acc0);
                    if (gr0 + 1 < N) op[(size_t)od]     = __uint_as_float((unsigned)(acc0 >> 32));
                    if (gr0 + 2 < N) op[2 * (size_t)od] = __uint_as_float((unsigned)acc1);
                    if (gr0 + 3 < N) op[3 * (size_t)od] = __uint_as_float((unsigned)(acc1 >> 32));
                }
            }
        }
    } else {
        // -------- correct-but-slow fallback (never taken for this generator) ----
        float* f1 = (float*)smraw;                 // [16][640]
        float* f2 = f1 + ROWS * REP;
        for (int i = tid; i < ROWS * REP; i += 1024) {
            int r = i / REP, c = i - r * REP;
            int gr = rowbase + r;
            f1[i] = (gr < N) ? x1[(size_t)gr * REP + c] : 0.f;
            f2[i] = (gr < N) ? x2[(size_t)gr * REP + c] : 0.f;
        }
        for (int i = tid; i < ROWS * out_dim; i += 1024) {
            int gr = rowbase + i / out_dim;
            if (gr < N) out[(size_t)gr * out_dim + (i % out_dim)] = 0.f;
        }
        __syncthreads();
        int is64 = g_is64;
        for (int e = tid; e < M; e += 1024) {
            int a = geti(r1, e, is64), b = geti(r2, e, is64), o = geti(ro, e, is64);
            float c = cg[e];
            if ((unsigned)a >= (unsigned)REP || (unsigned)b >= (unsigned)REP ||
                (unsigned)o >= (unsigned)out_dim) continue;
            for (int r = 0; r < ROWS; ++r) {
                int gr = rowbase + r;
                if (gr < N)
                    atomicAdd(&out[(size_t)gr * out_dim + o],
                              c * f1[r * REP + a] * f2[r * REP + b]);
            }
        }
    }
}

// -------- launcher --------
extern "C" void kernel_launch(void* const* d_in, const int* in_sizes, int n_in,
                              void* d_out, int out_size) {
    const float* x1 = (const float*)d_in[0];
    const float* x2 = (const float*)d_in[1];
    const float* cg = (const float*)d_in[2];
    const void*  r1 = d_in[3];
    const void*  r2 = d_in[4];
    const void*  ro = d_in[5];

    int M = in_sizes[2];
    int N = in_sizes[0] / REP;
    int out_dim = out_size / N;

    k_prep<<<1, 1024>>>(r1, r2, ro, cg, M, out_dim);

    int smem = 2 * NQUAD * REP * (int)sizeof(float4)           // 81920 tiles
             + MAXSTEP * (int)sizeof(uint2)                    // 8192 program
             + (NBIN + 1 + NSEG + 1) * (int)sizeof(int) + 16;  // ptrs
    cudaFuncSetAttribute(k_main, cudaFuncAttributeMaxDynamicSharedMemorySize, smem);
    k_main<<<(N + ROWS - 1) / ROWS, 1024, smem>>>(x1, x2, (float*)d_out,
                                                  N, out_dim, r1, r2, ro, cg, M);
}